// round 4
// baseline (speedup 1.0000x reference)
#include <cuda_runtime.h>
#include <cstdint>

#define LSEQ 512
#define UDIM 512
#define BDIM 4
#define HDIM 8
#define DDIM 64
#define HBDIM 32

typedef unsigned long long ull;

// ---------------- scratch (device globals, no allocation) ----------------
__device__ float g_Q[BDIM * LSEQ * UDIM];
__device__ float g_K[BDIM * LSEQ * UDIM];
__device__ float g_V[BDIM * LSEQ * UDIM];
__device__ float g_Wt[3 * UDIM * UDIM];   // W transposed: [z][n][k]
__device__ float g_qm[BDIM * LSEQ];

// ---------------- packed f32x2 + approx helpers ----------------
__device__ __forceinline__ void fma2(ull& d, ull a, ull b) {
    asm("fma.rn.f32x2 %0, %1, %2, %0;" : "+l"(d) : "l"(a), "l"(b));
}
__device__ __forceinline__ ull pk2(float x, float y) {
    ull r; asm("mov.b64 %0, {%1, %2};" : "=l"(r) : "f"(x), "f"(y)); return r;
}
__device__ __forceinline__ float2 upk(ull v) {
    float2 f; asm("mov.b64 {%0, %1}, %2;" : "=f"(f.x), "=f"(f.y) : "l"(v)); return f;
}
__device__ __forceinline__ float hsum(ull v) { float2 f = upk(v); return f.x + f.y; }
__device__ __forceinline__ float sqrt_ap(float x) {
    float r; asm("sqrt.approx.f32 %0, %1;" : "=f"(r) : "f"(x)); return r;
}
__device__ __forceinline__ float ex2_ap(float x) {
    float r; asm("ex2.approx.f32 %0, %1;" : "=f"(r) : "f"(x)); return r;
}

// ---------------- cp.async helpers ----------------
__device__ __forceinline__ void cpa16(void* sdst, const void* gsrc) {
    uint32_t s = (uint32_t)__cvta_generic_to_shared(sdst);
    asm volatile("cp.async.cg.shared.global [%0], [%1], 16;" :: "r"(s), "l"(gsrc));
}
#define CPA_COMMIT() asm volatile("cp.async.commit_group;")
#define CPA_WAIT(n)  asm volatile("cp.async.wait_group %0;" :: "n"(n))

// ---------------- kernel 0: transpose W (3 MB, once) ----------------
__global__ void transpose_w_kernel(const float* __restrict__ Wq,
                                   const float* __restrict__ Wk,
                                   const float* __restrict__ Wv) {
    __shared__ float t[32][33];
    const float* W = (blockIdx.z == 0) ? Wq : (blockIdx.z == 1) ? Wk : Wv;
    float* D = g_Wt + (size_t)blockIdx.z * UDIM * UDIM;
    int k0 = blockIdx.x * 32;
    int n0 = blockIdx.y * 32;
    int tx = threadIdx.x & 31, ty = threadIdx.x >> 5;
    #pragma unroll
    for (int i = 0; i < 4; i++) {
        int r = ty + i * 8;
        t[r][tx] = W[(size_t)(k0 + r) * UDIM + n0 + tx];
    }
    __syncthreads();
    #pragma unroll
    for (int i = 0; i < 4; i++) {
        int r = ty + i * 8;
        D[(size_t)(n0 + r) * UDIM + k0 + tx] = t[tx][r];
    }
}

// ---------------- kernel 1: fused GEMM + bias + relu (f32x2) ----------------
// C[2048x512] = relu(X @ W + b). BM=64, BN=64, BK=32, 256 thr, 4m x 4n/thread.
// Both operands k-contiguous; stride 36 floats (9 chunks, odd) -> conflict-free.
#define GBM 64
#define GBN 64
#define GBK 32
#define GST 36
#define GXSZ (GBM * GST)
#define GWSZ (GBN * GST)

__global__ __launch_bounds__(256, 2)
void qkv_gemm_kernel(const float* __restrict__ q_in,
                     const float* __restrict__ k_in,
                     const float* __restrict__ v_in,
                     const float* __restrict__ bq,
                     const float* __restrict__ bk,
                     const float* __restrict__ bv) {
    __shared__ float Xs[2][GXSZ];
    __shared__ float Ws[2][GWSZ];

    const float* X; const float* bias; float* dst;
    if (blockIdx.z == 0)      { X = q_in; bias = bq; dst = g_Q; }
    else if (blockIdx.z == 1) { X = k_in; bias = bk; dst = g_K; }
    else                      { X = v_in; bias = bv; dst = g_V; }
    const float* Wt = g_Wt + (size_t)blockIdx.z * UDIM * UDIM;

    const int tid = threadIdx.x;
    const int m0 = blockIdx.x * GBM;
    const int n0 = blockIdx.y * GBN;
    const int ty = tid >> 4;      // 16 groups -> m rows ty*4..+3 (broadcast reads)
    const int tx = tid & 15;      // n cols {tx + 16j} (phase rows consecutive)

    auto issue = [&](int t, int buf) {
        // X tile 64x32 = 512 chunks, 2/thread
        #pragma unroll
        for (int i = 0; i < 2; i++) {
            int lin = tid + i * 256;
            int r = lin >> 3, c = lin & 7;
            cpa16(&Xs[buf][r * GST + c * 4], X + (size_t)(m0 + r) * UDIM + t * GBK + c * 4);
        }
        // W tile 64x32 = 512 chunks, 2/thread
        #pragma unroll
        for (int i = 0; i < 2; i++) {
            int lin = tid + i * 256;
            int r = lin >> 3, c = lin & 7;
            cpa16(&Ws[buf][r * GST + c * 4], Wt + (size_t)(n0 + r) * UDIM + t * GBK + c * 4);
        }
        CPA_COMMIT();
    };

    ull acc[4][4] = {};
    issue(0, 0);

    for (int t = 0; t < 16; t++) {
        if (t < 15) { issue(t + 1, (t + 1) & 1); CPA_WAIT(1); }
        else        { CPA_WAIT(0); }
        __syncthreads();

        const float* xb = &Xs[t & 1][ty * 4 * GST];
        const float* wb = &Ws[t & 1][0];
        #pragma unroll
        for (int k4 = 0; k4 < 8; k4++) {
            ulonglong2 w[4];
            #pragma unroll
            for (int j = 0; j < 4; j++)
                w[j] = *(const ulonglong2*)(wb + (tx + 16 * j) * GST + k4 * 4);
            #pragma unroll
            for (int i = 0; i < 4; i++) {
                ulonglong2 a = *(const ulonglong2*)(xb + i * GST + k4 * 4);
                #pragma unroll
                for (int j = 0; j < 4; j++) {
                    fma2(acc[i][j], a.x, w[j].x);
                    fma2(acc[i][j], a.y, w[j].y);
                }
            }
        }
        __syncthreads();
    }

    float bv4[4];
    #pragma unroll
    for (int j = 0; j < 4; j++) bv4[j] = bias[n0 + tx + 16 * j];
    #pragma unroll
    for (int i = 0; i < 4; i++) {
        size_t mrow = (size_t)(m0 + ty * 4 + i) * UDIM;
        #pragma unroll
        for (int j = 0; j < 4; j++) {
            float v = hsum(acc[i][j]) + bv4[j];
            dst[mrow + n0 + tx + 16 * j] = v > 0.f ? v : 0.f;
        }
    }
}

// ---------------- kernel 2: query mask ----------------
__global__ void qm_kernel(const float* __restrict__ q_in) {
    int warp = (blockIdx.x * blockDim.x + threadIdx.x) >> 5;
    int lane = threadIdx.x & 31;
    if (warp >= BDIM * LSEQ) return;
    float s = 0.f;
    for (int e = lane; e < UDIM; e += 32) s += q_in[(size_t)warp * UDIM + e];
    #pragma unroll
    for (int o = 16; o; o >>= 1) s += __shfl_xor_sync(0xffffffffu, s, o);
    if (lane == 0) g_qm[warp] = (s != 0.f) ? 1.f : 0.f;
}

// ---------------- kernel 3: fused euclidean attention ----------------
// Block = 32 q-rows x one hb, 256 thr, 2 blocks/SM. 8 k-tiles of 64,
// 3-buffer K/V cp.async rotation (structure identical to the passing R3 kernel).
// Fixed-max softmax (scores <= 0). Per-thread: 2 q-rows x 4 k-cols / 4 d-cols.
#define A_QST 64
#define A_KST 68
#define A_SST 68
#define AOFF_Q  0
#define AOFF_KV (32 * A_QST)                      // 2048
#define AOFF_SS (AOFF_KV + 3 * 64 * A_KST)        // 2048 + 13056 = 15104
#define ATTN_SMEM_FLOATS (AOFF_SS + 32 * A_SST)   // 17280
#define ATTN_SMEM_BYTES (ATTN_SMEM_FLOATS * 4)    // 69120

__global__ __launch_bounds__(256, 2)
void attn_kernel(float* __restrict__ out, float* __restrict__ score_out) {
    extern __shared__ float smf[];
    float* Qs = smf + AOFF_Q;
    float* KV = smf + AOFF_KV;
    float* Ss = smf + AOFF_SS;

    const int tid = threadIdx.x;
    const int ty = tid >> 4;      // 0..15 -> 2 q-rows each (broadcast reads)
    const int tx = tid & 15;      // k-cols {tx + 16j} / d-cols tx*4..+3
    const int q0 = blockIdx.x * 32;
    const int hb = blockIdx.y;
    const int h = hb >> 2;        // hb = h*BDIM + b
    const int b = hb & 3;

    const float* Qg = g_Q + ((size_t)(b * LSEQ + q0)) * UDIM + h * DDIM;
    const float* Kg = g_K + ((size_t)(b * LSEQ)) * UDIM + h * DDIM;
    const float* Vg = g_V + ((size_t)(b * LSEQ)) * UDIM + h * DDIM;

    auto load_kv = [&](const float* src, float* dst) {
        #pragma unroll
        for (int i = 0; i < 4; i++) {
            int lin = tid + i * 256;
            int r = lin >> 4, c = lin & 15;
            cpa16(dst + r * A_KST + c * 4, src + (size_t)r * UDIM + c * 4);
        }
    };

    // group 0: Q + K0
    #pragma unroll
    for (int i = 0; i < 2; i++) {          // Q tile 32x64 = 512 chunks
        int lin = tid + i * 256;
        int r = lin >> 4, c = lin & 15;
        cpa16(Qs + r * A_QST + c * 4, Qg + (size_t)r * UDIM + c * 4);
    }
    load_kv(Kg, KV + 0 * 64 * A_KST);
    CPA_COMMIT();                                   // idx 0: Q+K0
    load_kv(Vg, KV + 1 * 64 * A_KST);
    CPA_COMMIT();                                   // idx 1: V0
    load_kv(Kg + (size_t)64 * UDIM, KV + 2 * 64 * A_KST);
    CPA_COMMIT();                                   // idx 2: K1

    float qm_r[2], l_acc[2];
    #pragma unroll
    for (int i = 0; i < 2; i++) {
        qm_r[i] = g_qm[b * LSEQ + q0 + ty * 2 + i];
        l_acc[i] = 0.f;
    }

    CPA_WAIT(2);           // Q+K0 done
    __syncthreads();

    // qq norms (Q reads are phase-broadcasts; redundant across tx, cheap)
    float qq[2];
    {
        ull qq2[2] = {};
        #pragma unroll
        for (int d4 = 0; d4 < 16; d4++) {
            #pragma unroll
            for (int i = 0; i < 2; i++) {
                ulonglong2 a = *(const ulonglong2*)(Qs + (ty * 2 + i) * A_QST + d4 * 4);
                fma2(qq2[i], a.x, a.x);
                fma2(qq2[i], a.y, a.y);
            }
        }
        #pragma unroll
        for (int i = 0; i < 2; i++) qq[i] = hsum(qq2[i]);
    }

    ull oacc[2][2] = {};     // 2 q-rows x 2 d-pairs (d = tx*4 .. tx*4+3)
    const float LOG2E = 1.4426950408889634f;

    for (int t = 0; t < 8; t++) {
        float* Kb = KV + ((2 * t) % 3) * 64 * A_KST;
        float* Vb = KV + ((2 * t + 1) % 3) * 64 * A_KST;

        // T_t: prefetch K_{t+1} into V_{t-1}'s slot
        if (t >= 1 && t <= 6)
            load_kv(Kg + (size_t)(t + 1) * 64 * UDIM, KV + ((2 * t + 2) % 3) * 64 * A_KST);
        CPA_COMMIT();                               // idx 3+2t
        CPA_WAIT(2);                                // K_t ready
        __syncthreads();

        // ---- S compute: dots + kk norms fused ----
        ull dot[2][4] = {};
        ull kk2[4] = {};
        #pragma unroll
        for (int d4 = 0; d4 < 16; d4++) {
            ulonglong2 kv4[4];
            #pragma unroll
            for (int j = 0; j < 4; j++) {
                kv4[j] = *(const ulonglong2*)(Kb + (tx + 16 * j) * A_KST + d4 * 4);
                fma2(kk2[j], kv4[j].x, kv4[j].x);
                fma2(kk2[j], kv4[j].y, kv4[j].y);
            }
            #pragma unroll
            for (int i = 0; i < 2; i++) {
                ulonglong2 a = *(const ulonglong2*)(Qs + (ty * 2 + i) * A_QST + d4 * 4);
                #pragma unroll
                for (int j = 0; j < 4; j++) {
                    fma2(dot[i][j], a.x, kv4[j].x);
                    fma2(dot[i][j], a.y, kv4[j].y);
                }
            }
        }
        float kk[4];
        #pragma unroll
        for (int j = 0; j < 4; j++) kk[j] = hsum(kk2[j]);

        #pragma unroll
        for (int i = 0; i < 2; i++) {
            int r = ty * 2 + i;
            size_t srow = ((size_t)(hb * LSEQ + q0 + r)) * LSEQ + t * 64;
            #pragma unroll
            for (int j = 0; j < 4; j++) {
                float d2 = fmaxf(qq[i] + kk[j] - 2.f * hsum(dot[i][j]), 1e-12f);
                float s = -sqrt_ap(d2) * 0.125f;
                score_out[srow + tx + 16 * j] = s * qm_r[i];
                float p = ex2_ap(s * LOG2E);
                Ss[r * A_SST + tx + 16 * j] = p;
                l_acc[i] += p;
            }
        }
        __syncthreads();     // Ss ready; Kb fully consumed

        // U_t: prefetch V_{t+1} into K_t's slot
        if (t < 7)
            load_kv(Vg + (size_t)(t + 1) * 64 * UDIM, KV + ((2 * t) % 3) * 64 * A_KST);
        CPA_COMMIT();                               // idx 4+2t
        CPA_WAIT(2);                                // V_t ready
        __syncthreads();

        // ---- PV accumulate: O += P * V ----
        #pragma unroll
        for (int k4 = 0; k4 < 16; k4++) {
            float4 p4[2];
            #pragma unroll
            for (int i = 0; i < 2; i++)
                p4[i] = *(const float4*)(Ss + (ty * 2 + i) * A_SST + k4 * 4);
            #pragma unroll
            for (int kk_ = 0; kk_ < 4; kk_++) {
                ulonglong2 v = *(const ulonglong2*)(Vb + (k4 * 4 + kk_) * A_KST + tx * 4);
                #pragma unroll
                for (int i = 0; i < 2; i++) {
                    float pe = ((const float*)&p4[i])[kk_];
                    ull p2 = pk2(pe, pe);
                    fma2(oacc[i][0], p2, v.x);
                    fma2(oacc[i][1], p2, v.y);
                }
            }
        }
        __syncthreads();     // V_t consumed before next T-load overwrite
    }

    // l reduction across the 16 tx lanes sharing each q-row
    #pragma unroll
    for (int i = 0; i < 2; i++) {
        #pragma unroll
        for (int o = 1; o < 16; o <<= 1)
            l_acc[i] += __shfl_xor_sync(0xffffffffu, l_acc[i], o);
    }

    // epilogue: out = (O / l) * qm, merged-head layout
    #pragma unroll
    for (int i = 0; i < 2; i++) {
        int r = ty * 2 + i;
        float scale = qm_r[i] / l_acc[i];
        float2 f0 = upk(oacc[i][0]);
        float2 f1 = upk(oacc[i][1]);
        float4 o;
        o.x = f0.x * scale; o.y = f0.y * scale;
        o.z = f1.x * scale; o.w = f1.y * scale;
        *(float4*)(out + ((size_t)(b * LSEQ + q0 + r)) * UDIM + h * DDIM + tx * 4) = o;
    }
}

// ---------------- launcher ----------------
extern "C" void kernel_launch(void* const* d_in, const int* in_sizes, int n_in,
                              void* d_out, int out_size) {
    (void)in_sizes; (void)n_in; (void)out_size;
    const float* queries = (const float*)d_in[0];
    const float* keys    = (const float*)d_in[1];
    const float* values  = (const float*)d_in[2];
    const float* Wq = (const float*)d_in[3];
    const float* bq = (const float*)d_in[4];
    const float* Wk = (const float*)d_in[5];
    const float* bk = (const float*)d_in[6];
    const float* Wv = (const float*)d_in[7];
    const float* bv = (const float*)d_in[8];

    float* out_ptr   = (float*)d_out;
    float* score_ptr = out_ptr + (size_t)BDIM * LSEQ * UDIM;

    cudaFuncSetAttribute(attn_kernel, cudaFuncAttributeMaxDynamicSharedMemorySize,
                         ATTN_SMEM_BYTES);

    dim3 tgrid(UDIM / 32, UDIM / 32, 3);
    transpose_w_kernel<<<tgrid, 256>>>(Wq, Wk, Wv);

    dim3 ggrid(BDIM * LSEQ / GBM, UDIM / GBN, 3);
    qkv_gemm_kernel<<<ggrid, 256>>>(queries, keys, values, bq, bk, bv);

    qm_kernel<<<(BDIM * LSEQ * 32) / 256, 256>>>(queries);

    dim3 agrid(LSEQ / 32, HBDIM);
    attn_kernel<<<agrid, 256, ATTN_SMEM_BYTES>>>(out_ptr, score_ptr);
}